// round 16
// baseline (speedup 1.0000x reference)
#include <cuda_runtime.h>
#include <cuda_bf16.h>
#include <math.h>

#define Hh 48
#define Ww 64
#define HW 3072
#define Cc 256
#define HIDDEN 128
#define CTX 64
#define CORR_DIM 324
#define GIN 516
#define NSAMP 37
#define SPLITK 6

__constant__ int c_lvlOff[4] = {0, 3072, 3840, 4032};
__constant__ int c_lvlH[4]   = {48, 24, 12, 6};
__constant__ int c_lvlW[4]   = {64, 32, 16, 8};

__constant__ float c_rot[12][3] = {
    {0,0,0},{0,0,0},{0,0,0},{0,0,0},{0,0,0},{0,0,0},
    {1,0,0},{-1,0,0},{0,1,0},{0,-1,0},{0,0,1},{0,0,-1}};
__constant__ float c_trs[12][3] = {
    {1,0,0},{-1,0,0},{0,1,0},{0,-1,0},{0,0,1},{0,0,-1},
    {0,0,0},{0,0,0},{0,0,0},{0,0,0},{0,0,0},{0,0,0}};
__constant__ float c_scales[3] = {0.25f, 1.0f, 4.0f};

__device__ float g_corr[HW * 3072];
__device__ float g_pyr1[HW * 768];
__device__ float g_pyr2[HW * 192];
__device__ float g_pyr3[HW * 48];
__device__ float g_sat0[HW * 3185];
__device__ float g_sat1[HW * 825];
__device__ float g_sat2[HW * 221];
__device__ float g_sat3[HW * 63];
__device__ float g_X[3 * HW];
__device__ float g_K[4];
__device__ float g_samp[NSAMP * 12];
__device__ float g_conf[NSAMP];
__device__ float g_pose[7];
__device__ float g_xin[(CORR_DIM + CTX) * HW];
__device__ float g_h[HIDDEN * HW];
__device__ float g_zg[HIDDEN * HW];
__device__ float g_rgh[HIDDEN * HW];
__device__ float g_feat[HIDDEN];
__device__ float g_pA[SPLITK * HIDDEN * HW];
__device__ float g_pB[SPLITK * HIDDEN * HW];
// bf16 weights in mma A-fragment order: [chunk][tap][ocfrag16][lane][4 x u32]
__device__ unsigned int g_wAz[33 * 9216];
__device__ unsigned int g_wAr[33 * 9216];
__device__ unsigned int g_wAq[33 * 9216];
__device__ unsigned int g_wAh[8 * 9216];

// ---- helpers ----
__device__ __forceinline__ unsigned int f2tf32(float f) {
    unsigned int r; asm("cvt.rna.tf32.f32 %0, %1;" : "=r"(r) : "f"(f)); return r;
}

__device__ __forceinline__ void qmul_d(const float* a, const float* b, float* o) {
    o[0] = a[0]*b[0] - a[1]*b[1] - a[2]*b[2] - a[3]*b[3];
    o[1] = a[0]*b[1] + a[1]*b[0] + a[2]*b[3] - a[3]*b[2];
    o[2] = a[0]*b[2] - a[1]*b[3] + a[2]*b[0] + a[3]*b[1];
    o[3] = a[0]*b[3] + a[1]*b[2] - a[2]*b[1] + a[3]*b[0];
}
__device__ __forceinline__ void qapply_d(const float* q, const float* v, float* o) {
    float qv[4] = {0.f, v[0], v[1], v[2]};
    float qc[4] = {q[0], -q[1], -q[2], -q[3]};
    float t[4], r[4];
    qmul_d(q, qv, t);
    qmul_d(t, qc, r);
    o[0] = r[1]; o[1] = r[2]; o[2] = r[3];
}

// common sample-prep body (pose in p[7])
__device__ __forceinline__ void sample_body(int n, const float* p) {
    float qc[4] = {p[0], p[1], p[2], p[3]};
    float tc[3] = {p[4], p[5], p[6]};
    float dq[4], dt[3];
    if (n < 36) {
        int b = n / 3, m = n % 3;
        float sc = c_scales[m];
        float rx = c_rot[b][0], ry = c_rot[b][1], rz = c_rot[b][2];
        float rn = sqrtf(rx * rx + ry * ry + rz * rz);
        float dnm = fmaxf(rn, 1e-8f);
        float ha = 0.02f * sc * 0.5f;
        float sh = sinf(ha);
        dq[0] = cosf(ha);
        dq[1] = rx / dnm * sh;
        dq[2] = ry / dnm * sh;
        dq[3] = rz / dnm * sh;
        float ts = 0.02f * sc;
        dt[0] = c_trs[b][0] * ts;
        dt[1] = c_trs[b][1] * ts;
        dt[2] = c_trs[b][2] * ts;
    } else {
        dq[0] = 1.f; dq[1] = 0.f; dq[2] = 0.f; dq[3] = 0.f;
        dt[0] = 0.f; dt[1] = 0.f; dt[2] = 0.f;
    }
    float q[4];
    qmul_d(qc, dq, q);
    float inv = rsqrtf(q[0]*q[0] + q[1]*q[1] + q[2]*q[2] + q[3]*q[3]);
    q[0] *= inv; q[1] *= inv; q[2] *= inv; q[3] *= inv;
    float rd[3];
    qapply_d(qc, dt, rd);
    float w = q[0], x = q[1], y = q[2], z = q[3];
    float* S = g_samp + n * 12;
    S[0] = 1.f - 2.f * (y * y + z * z);
    S[1] = 2.f * (x * y - w * z);
    S[2] = 2.f * (x * z + w * y);
    S[3] = 2.f * (x * y + w * z);
    S[4] = 1.f - 2.f * (x * x + z * z);
    S[5] = 2.f * (y * z - w * x);
    S[6] = 2.f * (x * z - w * y);
    S[7] = 2.f * (y * z + w * x);
    S[8] = 1.f - 2.f * (x * x + y * y);
    S[9]  = tc[0] + rd[0];
    S[10] = tc[1] + rd[1];
    S[11] = tc[2] + rd[2];
}

// merged setup: intrinsics/pose/X + zero h + ctx planes + iter0 sample prep
__global__ void k_setup(const float* __restrict__ depth, const float* __restrict__ intr,
                        const float* __restrict__ ctx) {
    int i = blockIdx.x * 256 + threadIdx.x;
    float fx = 60.0f + 40.0f * intr[0];
    float fy = 60.0f + 40.0f * intr[1];
    float cx = 32.0f + 4.0f * (intr[2] - 0.5f);
    float cy = 24.0f + 4.0f * (intr[3] - 0.5f);
    if (i == 0) {
        g_K[0] = fx; g_K[1] = fy; g_K[2] = cx; g_K[3] = cy;
        g_pose[0] = 1.f; g_pose[1] = 0.f; g_pose[2] = 0.f; g_pose[3] = 0.f;
        g_pose[4] = 0.f; g_pose[5] = 0.f; g_pose[6] = 0.f;
    }
    if (i < NSAMP) {
        g_conf[i] = 0.f;
        float p[7] = {1.f, 0.f, 0.f, 0.f, 0.f, 0.f, 0.f};
        sample_body(i, p);
    }
    if (i < HW) {
        float u = (float)(i % Ww);
        float v = (float)(i / Ww);
        float d = 4.0f + 20.0f * depth[i];
        g_X[i]          = (u - cx) / fx * d;
        g_X[HW + i]     = (v - cy) / fy * d;
        g_X[2 * HW + i] = d;
    }
    if (i < HIDDEN * HW) g_h[i] = 0.f;
    if (i < CTX * HW) g_xin[CORR_DIM * HW + i] = ctx[i];
}

// all 4 weight tensors -> bf16 A-fragment layout, one launch
__device__ __forceinline__ void wT2_body(const float* w, unsigned int* dst, int I, int idx) {
    int j = idx & 3;
    int l = (idx >> 2) & 31;
    int f = (idx >> 7) & 7;
    int rest = idx >> 10;
    int tap = rest % 9;
    int chunk = rest / 9;
    int oc = f * 16 + (l >> 2) + (j & 1) * 8;
    int k = 2 * (l & 3) + (j >> 1) * 8;
    int c = chunk * 16 + k;
    float e0 = (c < I) ? w[(oc * I + c) * 9 + tap] : 0.f;
    float e1 = (c + 1 < I) ? w[(oc * I + c + 1) * 9 + tap] : 0.f;
    unsigned int lo = __bfloat16_as_ushort(__float2bfloat16(e0));
    unsigned int hi = __bfloat16_as_ushort(__float2bfloat16(e1));
    dst[idx] = lo | (hi << 16);
}
__global__ void k_wTall(const float* __restrict__ Wz, const float* __restrict__ Wr,
                        const float* __restrict__ Wq, const float* __restrict__ Wh) {
    int idx = blockIdx.x * 256 + threadIdx.x;
    const int BIG = 33 * 9216;
    if (idx < BIG)                wT2_body(Wz, g_wAz, GIN, idx);
    else if (idx < 2 * BIG)       wT2_body(Wr, g_wAr, GIN, idx - BIG);
    else if (idx < 3 * BIG)       wT2_body(Wq, g_wAq, GIN, idx - 2 * BIG);
    else if (idx < 3 * BIG + 8 * 9216) wT2_body(Wh, g_wAh, 128, idx - 3 * BIG);
}

// ---------------------------------------------------------------------------
// corr via tf32 tensor cores
// ---------------------------------------------------------------------------
__global__ void __launch_bounds__(256) k_corrT(const float* __restrict__ A,
                                               const float* __restrict__ B) {
    __shared__ unsigned int As[16][72];
    __shared__ unsigned int Bs[16][72];
    int i0 = blockIdx.y * 64;
    int j0 = blockIdx.x * 64;
    int tid = threadIdx.x;
    int lane = tid & 31;
    int wid = tid >> 5;
    int mf = wid & 3;
    int nh = wid >> 2;
    float acc[4][4];
#pragma unroll
    for (int a = 0; a < 4; a++)
#pragma unroll
        for (int b = 0; b < 4; b++) acc[a][b] = 0.f;

    for (int k0 = 0; k0 < Cc; k0 += 16) {
        for (int t = tid; t < 1024; t += 256) {
            int kk = t >> 6, ii = t & 63;
            As[kk][ii] = f2tf32(A[(k0 + kk) * HW + i0 + ii]);
            Bs[kk][ii] = f2tf32(B[(k0 + kk) * HW + j0 + ii]);
        }
        __syncthreads();
#pragma unroll
        for (int s = 0; s < 2; s++) {
            int kb = s * 8;
            int ar = kb + (lane & 3);
            int ac = mf * 16 + (lane >> 2);
            unsigned int a0 = As[ar][ac];
            unsigned int a1 = As[ar][ac + 8];
            unsigned int a2 = As[ar + 4][ac];
            unsigned int a3 = As[ar + 4][ac + 8];
#pragma unroll
            for (int nf = 0; nf < 4; nf++) {
                int jc = nh * 32 + nf * 8 + (lane >> 2);
                unsigned int b0 = Bs[kb + (lane & 3)][jc];
                unsigned int b1 = Bs[kb + 4 + (lane & 3)][jc];
                asm volatile(
                    "mma.sync.aligned.m16n8k8.row.col.f32.tf32.tf32.f32 "
                    "{%0,%1,%2,%3}, {%4,%5,%6,%7}, {%8,%9}, {%0,%1,%2,%3};"
                    : "+f"(acc[nf][0]), "+f"(acc[nf][1]),
                      "+f"(acc[nf][2]), "+f"(acc[nf][3])
                    : "r"(a0), "r"(a1), "r"(a2), "r"(a3), "r"(b0), "r"(b1));
            }
        }
        __syncthreads();
    }
    int ib = i0 + mf * 16 + (lane >> 2);
#pragma unroll
    for (int nf = 0; nf < 4; nf++) {
        int j = j0 + nh * 32 + nf * 8 + (lane & 3) * 2;
        *(float2*)&g_corr[(long)ib * 3072 + j] =
            make_float2(acc[nf][0] * 0.0625f, acc[nf][1] * 0.0625f);
        *(float2*)&g_corr[(long)(ib + 8) * 3072 + j] =
            make_float2(acc[nf][2] * 0.0625f, acc[nf][3] * 0.0625f);
    }
}

// ---------------------------------------------------------------------------
// k_prep: per-pixel pyramid pooling + all 4 SATs in one pass (smem-resident)
// ---------------------------------------------------------------------------
__global__ void __launch_bounds__(128) k_prep() {
    int p = blockIdx.x;
    int t = threadIdx.x;
    __shared__ float row[3072];
    __shared__ float p1[768];
    __shared__ float p2[192];
    __shared__ float p3[48];
    __shared__ float s0[3185];
    __shared__ float s1[825];
    __shared__ float s2[221];
    __shared__ float s3[63];
    const float* src = g_corr + (long)p * 3072;
    for (int i = t; i < 3072; i += 128) row[i] = src[i];
    __syncthreads();
    for (int i = t; i < 768; i += 128) {
        int hy = i >> 5, wx = i & 31;
        int b = (hy * 2) * 64 + wx * 2;
        p1[i] = 0.25f * (row[b] + row[b + 1] + row[b + 64] + row[b + 65]);
    }
    __syncthreads();
    for (int i = t; i < 192; i += 128) {
        int hy = i >> 4, wx = i & 15;
        int b = (hy * 2) * 32 + wx * 2;
        p2[i] = 0.25f * (p1[b] + p1[b + 1] + p1[b + 32] + p1[b + 33]);
    }
    __syncthreads();
    if (t < 48) {
        int hy = t >> 3, wx = t & 7;
        int b = (hy * 2) * 16 + wx * 2;
        p3[t] = 0.25f * (p2[b] + p2[b + 1] + p2[b + 16] + p2[b + 17]);
    }
    // zero top rows
    if (t < 65) s0[t] = 0.f;
    if (t < 33) s1[t] = 0.f;
    if (t < 17) s2[t] = 0.f;
    if (t < 9)  s3[t] = 0.f;
    __syncthreads();
    // row prefixes (thread-partitioned per level)
    if (t < 48) {
        float run = 0.f; s0[(t + 1) * 65] = 0.f;
        for (int c = 0; c < 64; c++) { run += row[t * 64 + c]; s0[(t + 1) * 65 + c + 1] = run; }
    } else if (t < 72) {
        int r = t - 48; float run = 0.f; s1[(r + 1) * 33] = 0.f;
        for (int c = 0; c < 32; c++) { run += p1[r * 32 + c]; s1[(r + 1) * 33 + c + 1] = run; }
    } else if (t < 84) {
        int r = t - 72; float run = 0.f; s2[(r + 1) * 17] = 0.f;
        for (int c = 0; c < 16; c++) { run += p2[r * 16 + c]; s2[(r + 1) * 17 + c + 1] = run; }
    } else if (t < 90) {
        int r = t - 84; float run = 0.f; s3[(r + 1) * 9] = 0.f;
        for (int c = 0; c < 8; c++) { run += p3[r * 8 + c]; s3[(r + 1) * 9 + c + 1] = run; }
    }
    __syncthreads();
    // col prefixes
    if (t < 64) {
        int c = t + 1; float run = 0.f;
        for (int r = 1; r <= 48; r++) { run += s0[r * 65 + c]; s0[r * 65 + c] = run; }
    } else if (t < 96) {
        int c = t - 63; float run = 0.f;
        for (int r = 1; r <= 24; r++) { run += s1[r * 33 + c]; s1[r * 33 + c] = run; }
    } else if (t < 112) {
        int c = t - 95; float run = 0.f;
        for (int r = 1; r <= 12; r++) { run += s2[r * 17 + c]; s2[r * 17 + c] = run; }
    } else if (t < 120) {
        int c = t - 111; float run = 0.f;
        for (int r = 1; r <= 6; r++) { run += s3[r * 9 + c]; s3[r * 9 + c] = run; }
    }
    __syncthreads();
    // write out
    float* d;
    d = g_pyr1 + (long)p * 768;  for (int i = t; i < 768; i += 128) d[i] = p1[i];
    d = g_pyr2 + (long)p * 192;  for (int i = t; i < 192; i += 128) d[i] = p2[i];
    if (t < 48) g_pyr3[(long)p * 48 + t] = p3[t];
    d = g_sat0 + (long)p * 3185; for (int i = t; i < 3185; i += 128) d[i] = s0[i];
    d = g_sat1 + (long)p * 825;  for (int i = t; i < 825; i += 128) d[i] = s1[i];
    d = g_sat2 + (long)p * 221;  for (int i = t; i < 221; i += 128) d[i] = s2[i];
    d = g_sat3 + (long)p * 63;   for (int i = t; i < 63; i += 128) d[i] = s3[i];
}

__device__ __forceinline__ float satT(const float* S, int Hl, int Wl, int satW, int a, int b) {
    int c0 = min(max(a - 4, 0), Wl);
    int c1 = min(max(a + 5, 0), Wl);
    int r0 = min(max(b - 4, 0), Hl);
    int r1 = min(max(b + 5, 0), Hl);
    return S[r1 * satW + c1] - S[r0 * satW + c1] - S[r1 * satW + c0] + S[r0 * satW + c0];
}

__device__ __forceinline__ float confLevel(const float* S, int Hl, int Wl, int satW,
                                           float ul, float vl) {
    float bx = floorf(ul), by = floorf(vl);
    float fx = ul - bx, fy = vl - by;
    int ax = (int)bx, ay = (int)by;
    float T00 = satT(S, Hl, Wl, satW, ax,     ay);
    float T10 = satT(S, Hl, Wl, satW, ax + 1, ay);
    float T01 = satT(S, Hl, Wl, satW, ax,     ay + 1);
    float T11 = satT(S, Hl, Wl, satW, ax + 1, ay + 1);
    return (1.f - fx) * (1.f - fy) * T00 + fx * (1.f - fy) * T10
         + (1.f - fx) * fy * T01 + fx * fy * T11;
}

__global__ void k_conf() {
    int n = blockIdx.x;
    int chunk = blockIdx.y;           // 0..7, 384 px each
    __shared__ float sR[12];
    __shared__ float red[256];
    int tid = threadIdx.x;
    if (tid < 12) sR[tid] = g_samp[n * 12 + tid];
    __syncthreads();
    float fx = g_K[0], fy = g_K[1], cx = g_K[2], cy = g_K[3];
    float acc = 0.f;
    int p0 = chunk * 384;
    for (int p = p0 + tid; p < p0 + 384; p += 256) {
        float X = g_X[p], Y = g_X[HW + p], Z = g_X[2 * HW + p];
        float xc = sR[0] * X + sR[1] * Y + sR[2] * Z + sR[9];
        float yc = sR[3] * X + sR[4] * Y + sR[5] * Z + sR[10];
        float zc = sR[6] * X + sR[7] * Y + sR[8] * Z + sR[11];
        zc = fmaxf(zc, 0.1f);
        float u = fx * xc / zc + cx;
        float v = fy * yc / zc + cy;
        acc += confLevel(g_sat0 + (long)p * 3185, 48, 64, 65, u,          v);
        acc += confLevel(g_sat1 + (long)p * 825,  24, 32, 33, u * 0.5f,   v * 0.5f);
        acc += confLevel(g_sat2 + (long)p * 221,  12, 16, 17, u * 0.25f,  v * 0.25f);
        acc += confLevel(g_sat3 + (long)p * 63,    6,  8,  9, u * 0.125f, v * 0.125f);
    }
    red[tid] = acc;
    __syncthreads();
    for (int s = 128; s > 0; s >>= 1) {
        if (tid < s) red[tid] += red[tid + s];
        __syncthreads();
    }
    if (tid == 0) atomicAdd(&g_conf[n], red[0]);
}

// fused correlation features (top-3 recomputed per block) -> g_xin [0,324)
__global__ void k_fused() {
    int p = blockIdx.x;
    __shared__ float sRow[4080];
    __shared__ int   sTi[3];
    __shared__ float sWsel[3];
    __shared__ int   sBx[12], sBy[12];
    __shared__ float sFx[12], sFy[12], sWk[3];
    int tid = threadIdx.x;
    {
        const float* r0 = g_corr + (long)p * 3072;
        for (int i = tid; i < 3072; i += 128) sRow[i] = r0[i];
        const float* r1 = g_pyr1 + (long)p * 768;
        for (int i = tid; i < 768; i += 128) sRow[3072 + i] = r1[i];
        const float* r2 = g_pyr2 + (long)p * 192;
        for (int i = tid; i < 192; i += 128) sRow[3840 + i] = r2[i];
        const float* r3 = g_pyr3 + (long)p * 48;
        if (tid < 48) sRow[4032 + tid] = r3[tid];
    }
    if (tid == 0) {
        float v[NSAMP];
        for (int i = 0; i < NSAMP; i++) v[i] = g_conf[i] * (1.0f / 995328.0f);
        float tv[3]; int ti[3];
        for (int k = 0; k < 3; k++) {
            float best = -1e30f; int bi = 0;
            for (int i = 0; i < NSAMP; i++)
                if (v[i] > best) { best = v[i]; bi = i; }
            tv[k] = best; ti[k] = bi;
            v[bi] = -1e30f;
        }
        float m = tv[0];
        float e0 = expf(tv[0] - m), e1 = expf(tv[1] - m), e2 = expf(tv[2] - m);
        float s = e0 + e1 + e2;
        sTi[0] = ti[0]; sTi[1] = ti[1]; sTi[2] = ti[2];
        sWsel[0] = e0 / s; sWsel[1] = e1 / s; sWsel[2] = e2 / s;
    }
    __syncthreads();
    if (tid < 3) {
        int n = sTi[tid];
        sWk[tid] = sWsel[tid];
        const float* S = g_samp + n * 12;
        float X = g_X[p], Y = g_X[HW + p], Z = g_X[2 * HW + p];
        float xc = S[0] * X + S[1] * Y + S[2] * Z + S[9];
        float yc = S[3] * X + S[4] * Y + S[5] * Z + S[10];
        float zc = S[6] * X + S[7] * Y + S[8] * Z + S[11];
        zc = fmaxf(zc, 0.1f);
        float u = g_K[0] * xc / zc + g_K[2];
        float v = g_K[1] * yc / zc + g_K[3];
        float inv = 1.f;
        for (int l = 0; l < 4; l++) {
            float ul = u * inv, vl = v * inv;
            float bx = floorf(ul), by = floorf(vl);
            sBx[tid * 4 + l] = (int)bx;
            sBy[tid * 4 + l] = (int)by;
            sFx[tid * 4 + l] = ul - bx;
            sFy[tid * 4 + l] = vl - by;
            inv *= 0.5f;
        }
    }
    __syncthreads();
    for (int c = tid; c < CORR_DIM; c += 128) {
        int l = c / 81, o = c % 81;
        int oy = o / 9 - 4, ox = o % 9 - 4;
        const float* row = sRow + c_lvlOff[l];
        int Hl = c_lvlH[l], Wl = c_lvlW[l];
        float acc = 0.f;
#pragma unroll
        for (int k = 0; k < 3; k++) {
            int i = k * 4 + l;
            int x0 = sBx[i] + ox, y0 = sBy[i] + oy;
            float fxw = sFx[i], fyw = sFy[i];
            float s = 0.f;
            bool vx0 = (x0 >= 0 && x0 < Wl);
            bool vx1 = (x0 + 1 >= 0 && x0 + 1 < Wl);
            bool vy0 = (y0 >= 0 && y0 < Hl);
            bool vy1 = (y0 + 1 >= 0 && y0 + 1 < Hl);
            if (vx0 && vy0) s += (1.f - fxw) * (1.f - fyw) * row[y0 * Wl + x0];
            if (vx1 && vy0) s += fxw * (1.f - fyw) * row[y0 * Wl + x0 + 1];
            if (vx0 && vy1) s += (1.f - fxw) * fyw * row[(y0 + 1) * Wl + x0];
            if (vx1 && vy1) s += fxw * fyw * row[(y0 + 1) * Wl + x0 + 1];
            acc += sWk[k] * s;
        }
        g_xin[c * HW + p] = acc;
    }
}

// ---------------------------------------------------------------------------
// Conv: bf16 tensor-core implicit GEMM over taps (mma.sync.m16n8k16).
// mode 4 = merged z+r (grid z = 2*SPLITK); mode 3 = h-conv, splitK=1 with
// fused relu + spatial-reduce epilogue (atomicAdd into g_feat).
// ---------------------------------------------------------------------------
__device__ __forceinline__ void conv_loadch(float pf[17], const float* inA, const float* inB,
                                            int C, int chunk, int sc, int sp0, int y0) {
    int cg = chunk * 16 + sc;
    const float* plane = (cg < 128) ? (inA + cg * HW)
                       : ((cg < C) ? (inB + (cg - 128) * HW) : (const float*)0);
#pragma unroll
    for (int k = 0; k < 17; k++) {
        int px = sp0 + k * 16;
        float v = 0.f;
        if (px < 264 && plane) {
            int row = px / 66, xcol = px % 66;
            int yy = y0 - 1 + row, xx = xcol - 1;
            if (yy >= 0 && yy < Hh && xx >= 0 && xx < Ww) v = plane[yy * Ww + xx];
        }
        pf[k] = v;
    }
}
__device__ __forceinline__ void conv_storech(float pf[17], unsigned short* s,
                                             int sc, int sp0) {
#pragma unroll
    for (int k = 0; k < 17; k++) {
        int px = sp0 + k * 16;
        if (px < 264)
            s[px * 18 + sc] = __bfloat16_as_ushort(__float2bfloat16(pf[k]));
    }
}

__global__ void __launch_bounds__(256, 2) k_convT(int mode, const float* __restrict__ bias) {
    const float* inA; const float* inB; const unsigned int* wA; float* outP; int nch, C;
    if (mode == 0)      { inA = g_h;   inB = g_xin; wA = g_wAz; outP = g_pA; nch = 33; C = GIN; }
    else if (mode == 1) { inA = g_h;   inB = g_xin; wA = g_wAr; outP = g_pB; nch = 33; C = GIN; }
    else if (mode == 2) { inA = g_rgh; inB = g_xin; wA = g_wAq; outP = g_pA; nch = 33; C = GIN; }
    else if (mode == 3) { inA = g_h;   inB = g_h;   wA = g_wAh; outP = g_pB; nch = 8;  C = 128; }
    else {
        inA = g_h; inB = g_xin; nch = 33; C = GIN;
        if (blockIdx.z < SPLITK) { wA = g_wAz; outP = g_pA; }
        else                     { wA = g_wAr; outP = g_pB; }
    }

    const int y0 = blockIdx.y * 2;
    const int ocBase = blockIdx.x * 64;
    const int ns = (mode == 3) ? 1 : SPLITK;
    const int kz = (int)blockIdx.z % SPLITK;
    const int ch0 = kz * nch / ns;
    const int ch1 = (kz + 1) * nch / ns;
    outP += kz * HIDDEN * HW;

    const int tid = threadIdx.x;
    const int lane = tid & 31;
    const int wid = tid >> 5;
    const int mf = wid & 3;
    const int nb = (wid >> 2) * 8;
    const int fg = (ocBase >> 4) + mf;

    const int sc = tid >> 4;
    const int sp0 = tid & 15;

    __shared__ unsigned short sIn[2][264 * 18];

    float acc[8][4];
#pragma unroll
    for (int i = 0; i < 8; i++)
#pragma unroll
        for (int j = 0; j < 4; j++) acc[i][j] = 0.f;

    float pf[17];
    conv_loadch(pf, inA, inB, C, ch0, sc, sp0, y0);
    conv_storech(pf, sIn[0], sc, sp0);
    __syncthreads();

    const uint4* wA4 = (const uint4*)wA;

    for (int ch = ch0; ch < ch1; ch++) {
        const int b = (ch - ch0) & 1;
        const bool more = (ch + 1 < ch1);
        if (more) conv_loadch(pf, inA, inB, C, ch + 1, sc, sp0, y0);

        uint4 Acur = wA4[((ch * 9 + 0) * 8 + fg) * 32 + lane];
#pragma unroll
        for (int tap = 0; tap < 9; tap++) {
            uint4 Anext = Acur;
            if (tap < 8) Anext = wA4[((ch * 9 + tap + 1) * 8 + fg) * 32 + lane];
            const int dy = tap / 3, dx = tap % 3;
#pragma unroll
            for (int nf = 0; nf < 8; nf++) {
                int n = (nb + nf) * 8 + (lane >> 2);
                int r = n >> 6, x = n & 63;
                int pxs = (r + dy) * 66 + x + dx;
                const unsigned short* bp = &sIn[b][pxs * 18 + (lane & 3) * 2];
                unsigned int b0 = *(const unsigned int*)bp;
                unsigned int b1 = *(const unsigned int*)(bp + 8);
                asm volatile(
                    "mma.sync.aligned.m16n8k16.row.col.f32.bf16.bf16.f32 "
                    "{%0,%1,%2,%3}, {%4,%5,%6,%7}, {%8,%9}, {%0,%1,%2,%3};"
                    : "+f"(acc[nf][0]), "+f"(acc[nf][1]),
                      "+f"(acc[nf][2]), "+f"(acc[nf][3])
                    : "r"(Acur.x), "r"(Acur.y), "r"(Acur.z), "r"(Acur.w),
                      "r"(b0), "r"(b1));
            }
            Acur = Anext;
        }
        if (more) conv_storech(pf, sIn[b ^ 1], sc, sp0);
        __syncthreads();
    }

    const int oc0 = ocBase + mf * 16 + (lane >> 2);
    if (mode == 3) {
        // fused relu + spatial reduce -> g_feat (zeroed by k_comb_q)
        float b0v = bias[oc0];
        float b8v = bias[oc0 + 8];
        float sA = 0.f, sB = 0.f;
#pragma unroll
        for (int nf = 0; nf < 8; nf++) {
            sA += fmaxf(acc[nf][0] + b0v, 0.f) + fmaxf(acc[nf][1] + b0v, 0.f);
            sB += fmaxf(acc[nf][2] + b8v, 0.f) + fmaxf(acc[nf][3] + b8v, 0.f);
        }
        sA += __shfl_xor_sync(0xffffffff, sA, 1);
        sA += __shfl_xor_sync(0xffffffff, sA, 2);
        sB += __shfl_xor_sync(0xffffffff, sB, 1);
        sB += __shfl_xor_sync(0xffffffff, sB, 2);
        if ((lane & 3) == 0) {
            atomicAdd(&g_feat[oc0], sA);
            atomicAdd(&g_feat[oc0 + 8], sB);
        }
        return;
    }
#pragma unroll
    for (int nf = 0; nf < 8; nf++) {
        int n = (nb + nf) * 8 + (lane & 3) * 2;
        int r = n >> 6, x = n & 63;
        float* o0 = &outP[oc0 * HW + (y0 + r) * Ww + x];
        *(float2*)o0 = make_float2(acc[nf][0], acc[nf][1]);
        *(float2*)(o0 + 8 * HW) = make_float2(acc[nf][2], acc[nf][3]);
    }
}

__device__ __forceinline__ float sum6(const float* P, int i) {
    float s = P[i];
#pragma unroll
    for (int k = 1; k < SPLITK; k++) s += P[i + k * HIDDEN * HW];
    return s;
}

__global__ void k_comb_zr(const float* __restrict__ bz, const float* __restrict__ br) {
    int i = blockIdx.x * 256 + threadIdx.x;
    int oc = i / HW;
    float z = sum6(g_pA, i) + bz[oc];
    z = 1.f / (1.f + expf(-z));
    float rr = sum6(g_pB, i) + br[oc];
    rr = 1.f / (1.f + expf(-rr));
    g_zg[i] = z;
    g_rgh[i] = rr * g_h[i];
}

__global__ void k_comb_q(const float* __restrict__ bq) {
    int i = blockIdx.x * 256 + threadIdx.x;
    int oc = i / HW;
    float q = sum6(g_pA, i) + bq[oc];
    q = tanhf(q);
    float z = g_zg[i];
    g_h[i] = (1.f - z) * g_h[i] + z * q;
    if (i < HIDDEN) g_feat[i] = 0.f;
}

// pose update + next-iter sample prep (fused)
__global__ void k_pose(const float* __restrict__ Wfc, const float* __restrict__ bfc,
                       float* __restrict__ outp, int writeOut) {
    __shared__ float red[128];
    __shared__ float sdelta[7];
    __shared__ float sP[7];
    int t = threadIdx.x;
    float fm = g_feat[t] * (1.0f / 3072.0f);
    for (int j = 0; j < 7; j++) {
        red[t] = fm * Wfc[t * 7 + j];
        __syncthreads();
        for (int s = 64; s > 0; s >>= 1) {
            if (t < s) red[t] += red[t + s];
            __syncthreads();
        }
        if (t == 0) sdelta[j] = 0.01f * (red[0] + bfc[j]);
        __syncthreads();
    }
    if (t == 0) {
        float qc[4] = {g_pose[0], g_pose[1], g_pose[2], g_pose[3]};
        float tc[3] = {g_pose[4], g_pose[5], g_pose[6]};
        float dq[4] = {1.f + sdelta[0], sdelta[1], sdelta[2], sdelta[3]};
        float inv = rsqrtf(dq[0]*dq[0] + dq[1]*dq[1] + dq[2]*dq[2] + dq[3]*dq[3]);
        dq[0] *= inv; dq[1] *= inv; dq[2] *= inv; dq[3] *= inv;
        float dv[3] = {sdelta[4], sdelta[5], sdelta[6]};
        float rv[3];
        qapply_d(qc, dv, rv);
        float tn[3] = {tc[0] + rv[0], tc[1] + rv[1], tc[2] + rv[2]};
        float qn[4];
        qmul_d(qc, dq, qn);
        float inv2 = rsqrtf(qn[0]*qn[0] + qn[1]*qn[1] + qn[2]*qn[2] + qn[3]*qn[3]);
        qn[0] *= inv2; qn[1] *= inv2; qn[2] *= inv2; qn[3] *= inv2;
        g_pose[0] = qn[0]; g_pose[1] = qn[1]; g_pose[2] = qn[2]; g_pose[3] = qn[3];
        g_pose[4] = tn[0]; g_pose[5] = tn[1]; g_pose[6] = tn[2];
        sP[0] = qn[0]; sP[1] = qn[1]; sP[2] = qn[2]; sP[3] = qn[3];
        sP[4] = tn[0]; sP[5] = tn[1]; sP[6] = tn[2];
        if (writeOut) {
            outp[0] = qn[0]; outp[1] = qn[1]; outp[2] = qn[2]; outp[3] = qn[3];
            outp[4] = tn[0]; outp[5] = tn[1]; outp[6] = tn[2];
        }
    }
    __syncthreads();
    if (t < NSAMP) {
        g_conf[t] = 0.f;
        float p[7];
#pragma unroll
        for (int k = 0; k < 7; k++) p[k] = sP[k];
        sample_body(t, p);
    }
}

extern "C" void kernel_launch(void* const* d_in, const int* in_sizes, int n_in,
                              void* d_out, int out_size) {
    const float* fmap_rgb   = (const float*)d_in[0];
    const float* fmap_depth = (const float*)d_in[1];
    const float* depth      = (const float*)d_in[2];
    const float* context    = (const float*)d_in[3];
    const float* intr       = (const float*)d_in[4];
    const float* Wz  = (const float*)d_in[5];
    const float* bz  = (const float*)d_in[6];
    const float* Wr  = (const float*)d_in[7];
    const float* br  = (const float*)d_in[8];
    const float* Wq  = (const float*)d_in[9];
    const float* bq  = (const float*)d_in[10];
    const float* Wh  = (const float*)d_in[11];
    const float* bh  = (const float*)d_in[12];
    const float* Wfc = (const float*)d_in[13];
    const float* bfc = (const float*)d_in[14];
    float* outp = (float*)d_out;

    dim3 cgrid(2, 24, SPLITK);
    dim3 cgrid2(2, 24, 2 * SPLITK);
    dim3 cgridH(2, 24, 1);

    k_setup<<<1536, 256>>>(depth, intr, context);           // 0
    k_wTall<<<3852, 256>>>(Wz, Wr, Wq, Wh);                 // 1
    k_corrT<<<dim3(48, 48), 256>>>(fmap_depth, fmap_rgb);   // 2
    k_prep<<<3072, 128>>>();                                // 3

    for (int it = 0; it < 4; it++) {
        k_conf<<<dim3(37, 8), 256>>>();          // my idx 4 on iter 0 -> ncu slot
        k_fused<<<3072, 128>>>();
        k_convT<<<cgrid2, 256>>>(4, bz);         // z + r merged
        k_comb_zr<<<1536, 256>>>(bz, br);
        k_convT<<<cgrid, 256>>>(2, bq);
        k_comb_q<<<1536, 256>>>(bq);
        k_convT<<<cgridH, 256>>>(3, bh);         // h-conv + fused relu/reduce
        k_pose<<<1, 128>>>(Wfc, bfc, outp, it == 3 ? 1 : 0);
    }
}

// round 17
// speedup vs baseline: 1.0639x; 1.0639x over previous
#include <cuda_runtime.h>
#include <cuda_bf16.h>
#include <math.h>

#define Hh 48
#define Ww 64
#define HW 3072
#define Cc 256
#define HIDDEN 128
#define CTX 64
#define CORR_DIM 324
#define GIN 516
#define NSAMP 37
#define SPLITK 6

__constant__ int c_lvlH[4]   = {48, 24, 12, 6};
__constant__ int c_lvlW[4]   = {64, 32, 16, 8};

__constant__ float c_rot[12][3] = {
    {0,0,0},{0,0,0},{0,0,0},{0,0,0},{0,0,0},{0,0,0},
    {1,0,0},{-1,0,0},{0,1,0},{0,-1,0},{0,0,1},{0,0,-1}};
__constant__ float c_trs[12][3] = {
    {1,0,0},{-1,0,0},{0,1,0},{0,-1,0},{0,0,1},{0,0,-1},
    {0,0,0},{0,0,0},{0,0,0},{0,0,0},{0,0,0},{0,0,0}};
__constant__ float c_scales[3] = {0.25f, 1.0f, 4.0f};

__device__ float g_corr[HW * 3072];
__device__ float g_pyr1[HW * 768];
__device__ float g_pyr2[HW * 192];
__device__ float g_pyr3[HW * 48];
__device__ float g_sat0[HW * 3185];
__device__ float g_sat1[HW * 825];
__device__ float g_sat2[HW * 221];
__device__ float g_sat3[HW * 63];
__device__ float g_X[3 * HW];
__device__ float g_K[4];
__device__ float g_samp[NSAMP * 12];
__device__ float g_conf[NSAMP];
__device__ float g_pose[7];
__device__ float g_xin[(CORR_DIM + CTX) * HW];
__device__ float g_h[HIDDEN * HW];
__device__ float g_zg[HIDDEN * HW];
__device__ float g_rgh[HIDDEN * HW];
__device__ float g_feat[HIDDEN];
__device__ float g_pA[SPLITK * HIDDEN * HW];
__device__ float g_pB[SPLITK * HIDDEN * HW];
// bf16 weights in mma A-fragment order: [chunk][tap][ocfrag16][lane][4 x u32]
__device__ unsigned int g_wAz[33 * 9216];
__device__ unsigned int g_wAr[33 * 9216];
__device__ unsigned int g_wAq[33 * 9216];
__device__ unsigned int g_wAh[8 * 9216];

// ---- helpers ----
__device__ __forceinline__ unsigned int f2tf32(float f) {
    unsigned int r; asm("cvt.rna.tf32.f32 %0, %1;" : "=r"(r) : "f"(f)); return r;
}

__device__ __forceinline__ void qmul_d(const float* a, const float* b, float* o) {
    o[0] = a[0]*b[0] - a[1]*b[1] - a[2]*b[2] - a[3]*b[3];
    o[1] = a[0]*b[1] + a[1]*b[0] + a[2]*b[3] - a[3]*b[2];
    o[2] = a[0]*b[2] - a[1]*b[3] + a[2]*b[0] + a[3]*b[1];
    o[3] = a[0]*b[3] + a[1]*b[2] - a[2]*b[1] + a[3]*b[0];
}
__device__ __forceinline__ void qapply_d(const float* q, const float* v, float* o) {
    float qv[4] = {0.f, v[0], v[1], v[2]};
    float qc[4] = {q[0], -q[1], -q[2], -q[3]};
    float t[4], r[4];
    qmul_d(q, qv, t);
    qmul_d(t, qc, r);
    o[0] = r[1]; o[1] = r[2]; o[2] = r[3];
}

__device__ __forceinline__ void sample_body(int n, const float* p) {
    float qc[4] = {p[0], p[1], p[2], p[3]};
    float tc[3] = {p[4], p[5], p[6]};
    float dq[4], dt[3];
    if (n < 36) {
        int b = n / 3, m = n % 3;
        float sc = c_scales[m];
        float rx = c_rot[b][0], ry = c_rot[b][1], rz = c_rot[b][2];
        float rn = sqrtf(rx * rx + ry * ry + rz * rz);
        float dnm = fmaxf(rn, 1e-8f);
        float ha = 0.02f * sc * 0.5f;
        float sh = sinf(ha);
        dq[0] = cosf(ha);
        dq[1] = rx / dnm * sh;
        dq[2] = ry / dnm * sh;
        dq[3] = rz / dnm * sh;
        float ts = 0.02f * sc;
        dt[0] = c_trs[b][0] * ts;
        dt[1] = c_trs[b][1] * ts;
        dt[2] = c_trs[b][2] * ts;
    } else {
        dq[0] = 1.f; dq[1] = 0.f; dq[2] = 0.f; dq[3] = 0.f;
        dt[0] = 0.f; dt[1] = 0.f; dt[2] = 0.f;
    }
    float q[4];
    qmul_d(qc, dq, q);
    float inv = rsqrtf(q[0]*q[0] + q[1]*q[1] + q[2]*q[2] + q[3]*q[3]);
    q[0] *= inv; q[1] *= inv; q[2] *= inv; q[3] *= inv;
    float rd[3];
    qapply_d(qc, dt, rd);
    float w = q[0], x = q[1], y = q[2], z = q[3];
    float* S = g_samp + n * 12;
    S[0] = 1.f - 2.f * (y * y + z * z);
    S[1] = 2.f * (x * y - w * z);
    S[2] = 2.f * (x * z + w * y);
    S[3] = 2.f * (x * y + w * z);
    S[4] = 1.f - 2.f * (x * x + z * z);
    S[5] = 2.f * (y * z - w * x);
    S[6] = 2.f * (x * z - w * y);
    S[7] = 2.f * (y * z + w * x);
    S[8] = 1.f - 2.f * (x * x + y * y);
    S[9]  = tc[0] + rd[0];
    S[10] = tc[1] + rd[1];
    S[11] = tc[2] + rd[2];
}

// merged setup: intrinsics/pose/X + zero h + ctx planes + iter0 sample prep
__global__ void k_setup(const float* __restrict__ depth, const float* __restrict__ intr,
                        const float* __restrict__ ctx) {
    int i = blockIdx.x * 256 + threadIdx.x;
    float fx = 60.0f + 40.0f * intr[0];
    float fy = 60.0f + 40.0f * intr[1];
    float cx = 32.0f + 4.0f * (intr[2] - 0.5f);
    float cy = 24.0f + 4.0f * (intr[3] - 0.5f);
    if (i == 0) {
        g_K[0] = fx; g_K[1] = fy; g_K[2] = cx; g_K[3] = cy;
        g_pose[0] = 1.f; g_pose[1] = 0.f; g_pose[2] = 0.f; g_pose[3] = 0.f;
        g_pose[4] = 0.f; g_pose[5] = 0.f; g_pose[6] = 0.f;
    }
    if (i < NSAMP) {
        g_conf[i] = 0.f;
        float p[7] = {1.f, 0.f, 0.f, 0.f, 0.f, 0.f, 0.f};
        sample_body(i, p);
    }
    if (i < HW) {
        float u = (float)(i % Ww);
        float v = (float)(i / Ww);
        float d = 4.0f + 20.0f * depth[i];
        g_X[i]          = (u - cx) / fx * d;
        g_X[HW + i]     = (v - cy) / fy * d;
        g_X[2 * HW + i] = d;
    }
    if (i < HIDDEN * HW) g_h[i] = 0.f;
    if (i < CTX * HW) g_xin[CORR_DIM * HW + i] = ctx[i];
}

// all 4 weight tensors -> bf16 A-fragment layout, one launch
__device__ __forceinline__ void wT2_body(const float* w, unsigned int* dst, int I, int idx) {
    int j = idx & 3;
    int l = (idx >> 2) & 31;
    int f = (idx >> 7) & 7;
    int rest = idx >> 10;
    int tap = rest % 9;
    int chunk = rest / 9;
    int oc = f * 16 + (l >> 2) + (j & 1) * 8;
    int k = 2 * (l & 3) + (j >> 1) * 8;
    int c = chunk * 16 + k;
    float e0 = (c < I) ? w[(oc * I + c) * 9 + tap] : 0.f;
    float e1 = (c + 1 < I) ? w[(oc * I + c + 1) * 9 + tap] : 0.f;
    unsigned int lo = __bfloat16_as_ushort(__float2bfloat16(e0));
    unsigned int hi = __bfloat16_as_ushort(__float2bfloat16(e1));
    dst[idx] = lo | (hi << 16);
}
__global__ void k_wTall(const float* __restrict__ Wz, const float* __restrict__ Wr,
                        const float* __restrict__ Wq, const float* __restrict__ Wh) {
    int idx = blockIdx.x * 256 + threadIdx.x;
    const int BIG = 33 * 9216;
    if (idx < BIG)                wT2_body(Wz, g_wAz, GIN, idx);
    else if (idx < 2 * BIG)       wT2_body(Wr, g_wAr, GIN, idx - BIG);
    else if (idx < 3 * BIG)       wT2_body(Wq, g_wAq, GIN, idx - 2 * BIG);
    else if (idx < 3 * BIG + 8 * 9216) wT2_body(Wh, g_wAh, 128, idx - 3 * BIG);
}

// ---------------------------------------------------------------------------
// corr via tf32 tensor cores
// ---------------------------------------------------------------------------
__global__ void __launch_bounds__(256) k_corrT(const float* __restrict__ A,
                                               const float* __restrict__ B) {
    __shared__ unsigned int As[16][72];
    __shared__ unsigned int Bs[16][72];
    int i0 = blockIdx.y * 64;
    int j0 = blockIdx.x * 64;
    int tid = threadIdx.x;
    int lane = tid & 31;
    int wid = tid >> 5;
    int mf = wid & 3;
    int nh = wid >> 2;
    float acc[4][4];
#pragma unroll
    for (int a = 0; a < 4; a++)
#pragma unroll
        for (int b = 0; b < 4; b++) acc[a][b] = 0.f;

    for (int k0 = 0; k0 < Cc; k0 += 16) {
        for (int t = tid; t < 1024; t += 256) {
            int kk = t >> 6, ii = t & 63;
            As[kk][ii] = f2tf32(A[(k0 + kk) * HW + i0 + ii]);
            Bs[kk][ii] = f2tf32(B[(k0 + kk) * HW + j0 + ii]);
        }
        __syncthreads();
#pragma unroll
        for (int s = 0; s < 2; s++) {
            int kb = s * 8;
            int ar = kb + (lane & 3);
            int ac = mf * 16 + (lane >> 2);
            unsigned int a0 = As[ar][ac];
            unsigned int a1 = As[ar][ac + 8];
            unsigned int a2 = As[ar + 4][ac];
            unsigned int a3 = As[ar + 4][ac + 8];
#pragma unroll
            for (int nf = 0; nf < 4; nf++) {
                int jc = nh * 32 + nf * 8 + (lane >> 2);
                unsigned int b0 = Bs[kb + (lane & 3)][jc];
                unsigned int b1 = Bs[kb + 4 + (lane & 3)][jc];
                asm volatile(
                    "mma.sync.aligned.m16n8k8.row.col.f32.tf32.tf32.f32 "
                    "{%0,%1,%2,%3}, {%4,%5,%6,%7}, {%8,%9}, {%0,%1,%2,%3};"
                    : "+f"(acc[nf][0]), "+f"(acc[nf][1]),
                      "+f"(acc[nf][2]), "+f"(acc[nf][3])
                    : "r"(a0), "r"(a1), "r"(a2), "r"(a3), "r"(b0), "r"(b1));
            }
        }
        __syncthreads();
    }
    int ib = i0 + mf * 16 + (lane >> 2);
#pragma unroll
    for (int nf = 0; nf < 4; nf++) {
        int j = j0 + nh * 32 + nf * 8 + (lane & 3) * 2;
        *(float2*)&g_corr[(long)ib * 3072 + j] =
            make_float2(acc[nf][0] * 0.0625f, acc[nf][1] * 0.0625f);
        *(float2*)&g_corr[(long)(ib + 8) * 3072 + j] =
            make_float2(acc[nf][2] * 0.0625f, acc[nf][3] * 0.0625f);
    }
}

// separate pool + sat (reverted from merged k_prep; better occupancy)
__global__ void k_pool(int level) {
    const float* src; float* dst; int Hs, Ws;
    if (level == 1)      { src = g_corr; dst = g_pyr1; Hs = 48; Ws = 64; }
    else if (level == 2) { src = g_pyr1; dst = g_pyr2; Hs = 24; Ws = 32; }
    else                 { src = g_pyr2; dst = g_pyr3; Hs = 12; Ws = 16; }
    int Hd = Hs >> 1, Wd = Ws >> 1;
    int per = Hd * Wd;
    long idx = (long)blockIdx.x * 256 + threadIdx.x;
    if (idx >= (long)HW * per) return;
    int p = (int)(idx / per), r = (int)(idx % per);
    int hy = r / Wd, wx = r % Wd;
    const float* s = src + (long)p * (Hs * Ws);
    int b = (2 * hy) * Ws + 2 * wx;
    dst[idx] = 0.25f * (s[b] + s[b + 1] + s[b + Ws] + s[b + Ws + 1]);
}

__global__ void k_sat(int level) {
    const float* src; float* dstA; int Hl, Wl;
    if (level == 0)      { src = g_corr; dstA = g_sat0; Hl = 48; Wl = 64; }
    else if (level == 1) { src = g_pyr1; dstA = g_sat1; Hl = 24; Wl = 32; }
    else if (level == 2) { src = g_pyr2; dstA = g_sat2; Hl = 12; Wl = 16; }
    else                 { src = g_pyr3; dstA = g_sat3; Hl = 6;  Wl = 8;  }
    __shared__ float S[3185];
    int p = blockIdx.x;
    int satW = Wl + 1;
    int total = (Hl + 1) * satW;
    const float* s = src + (long)p * (Hl * Wl);
    int t = threadIdx.x;
    for (int c = t; c < satW; c += 128) S[c] = 0.f;
    if (t < Hl) {
        float run = 0.f;
        S[(t + 1) * satW] = 0.f;
        for (int c = 0; c < Wl; c++) {
            run += s[t * Wl + c];
            S[(t + 1) * satW + c + 1] = run;
        }
    }
    __syncthreads();
    if (t >= 1 && t <= Wl) {
        float run = 0.f;
        for (int r = 1; r <= Hl; r++) {
            run += S[r * satW + t];
            S[r * satW + t] = run;
        }
    }
    __syncthreads();
    float* D = dstA + (long)p * total;
    for (int i = t; i < total; i += 128) D[i] = S[i];
}

__device__ __forceinline__ float satT(const float* S, int Hl, int Wl, int satW, int a, int b) {
    int c0 = min(max(a - 4, 0), Wl);
    int c1 = min(max(a + 5, 0), Wl);
    int r0 = min(max(b - 4, 0), Hl);
    int r1 = min(max(b + 5, 0), Hl);
    return S[r1 * satW + c1] - S[r0 * satW + c1] - S[r1 * satW + c0] + S[r0 * satW + c0];
}

__device__ __forceinline__ float confLevel(const float* S, int Hl, int Wl, int satW,
                                           float ul, float vl) {
    float bx = floorf(ul), by = floorf(vl);
    float fx = ul - bx, fy = vl - by;
    int ax = (int)bx, ay = (int)by;
    float T00 = satT(S, Hl, Wl, satW, ax,     ay);
    float T10 = satT(S, Hl, Wl, satW, ax + 1, ay);
    float T01 = satT(S, Hl, Wl, satW, ax,     ay + 1);
    float T11 = satT(S, Hl, Wl, satW, ax + 1, ay + 1);
    return (1.f - fx) * (1.f - fy) * T00 + fx * (1.f - fy) * T10
         + (1.f - fx) * fy * T01 + fx * fy * T11;
}

__global__ void k_conf() {
    int n = blockIdx.x;
    int chunk = blockIdx.y;           // 0..7, 384 px each
    __shared__ float sR[12];
    __shared__ float red[256];
    int tid = threadIdx.x;
    if (tid < 12) sR[tid] = g_samp[n * 12 + tid];
    __syncthreads();
    float fx = g_K[0], fy = g_K[1], cx = g_K[2], cy = g_K[3];
    float acc = 0.f;
    int p0 = chunk * 384;
    for (int p = p0 + tid; p < p0 + 384; p += 256) {
        float X = g_X[p], Y = g_X[HW + p], Z = g_X[2 * HW + p];
        float xc = sR[0] * X + sR[1] * Y + sR[2] * Z + sR[9];
        float yc = sR[3] * X + sR[4] * Y + sR[5] * Z + sR[10];
        float zc = sR[6] * X + sR[7] * Y + sR[8] * Z + sR[11];
        zc = fmaxf(zc, 0.1f);
        float u = fx * xc / zc + cx;
        float v = fy * yc / zc + cy;
        acc += confLevel(g_sat0 + (long)p * 3185, 48, 64, 65, u,          v);
        acc += confLevel(g_sat1 + (long)p * 825,  24, 32, 33, u * 0.5f,   v * 0.5f);
        acc += confLevel(g_sat2 + (long)p * 221,  12, 16, 17, u * 0.25f,  v * 0.25f);
        acc += confLevel(g_sat3 + (long)p * 63,    6,  8,  9, u * 0.125f, v * 0.125f);
    }
    red[tid] = acc;
    __syncthreads();
    for (int s = 128; s > 0; s >>= 1) {
        if (tid < s) red[tid] += red[tid + s];
        __syncthreads();
    }
    if (tid == 0) atomicAdd(&g_conf[n], red[0]);
}

// ---------------------------------------------------------------------------
// fused correlation features via compact 10x10 window tiles per (sample,level)
// (zero-filled OOB == reference validity masking) -> g_xin [0,324)
// ---------------------------------------------------------------------------
__global__ void __launch_bounds__(128) k_fused() {
    int p = blockIdx.x;
    __shared__ int   sTi[3];
    __shared__ float sWsel[3];
    __shared__ int   sBx[12], sBy[12];
    __shared__ float sFx[12], sFy[12], sWk[3];
    __shared__ float sT[12][100];
    int tid = threadIdx.x;
    if (tid == 0) {
        float v[NSAMP];
        for (int i = 0; i < NSAMP; i++) v[i] = g_conf[i] * (1.0f / 995328.0f);
        float tv[3]; int ti[3];
        for (int k = 0; k < 3; k++) {
            float best = -1e30f; int bi = 0;
            for (int i = 0; i < NSAMP; i++)
                if (v[i] > best) { best = v[i]; bi = i; }
            tv[k] = best; ti[k] = bi;
            v[bi] = -1e30f;
        }
        float m = tv[0];
        float e0 = expf(tv[0] - m), e1 = expf(tv[1] - m), e2 = expf(tv[2] - m);
        float s = e0 + e1 + e2;
        sTi[0] = ti[0]; sTi[1] = ti[1]; sTi[2] = ti[2];
        sWsel[0] = e0 / s; sWsel[1] = e1 / s; sWsel[2] = e2 / s;
    }
    __syncthreads();
    if (tid < 3) {
        int n = sTi[tid];
        sWk[tid] = sWsel[tid];
        const float* S = g_samp + n * 12;
        float X = g_X[p], Y = g_X[HW + p], Z = g_X[2 * HW + p];
        float xc = S[0] * X + S[1] * Y + S[2] * Z + S[9];
        float yc = S[3] * X + S[4] * Y + S[5] * Z + S[10];
        float zc = S[6] * X + S[7] * Y + S[8] * Z + S[11];
        zc = fmaxf(zc, 0.1f);
        float u = g_K[0] * xc / zc + g_K[2];
        float v = g_K[1] * yc / zc + g_K[3];
        float inv = 1.f;
        for (int l = 0; l < 4; l++) {
            float ul = u * inv, vl = v * inv;
            float bx = floorf(ul), by = floorf(vl);
            sBx[tid * 4 + l] = (int)bx;
            sBy[tid * 4 + l] = (int)by;
            sFx[tid * 4 + l] = ul - bx;
            sFy[tid * 4 + l] = vl - by;
            inv *= 0.5f;
        }
    }
    __syncthreads();
    // load 12 window tiles (10x10 each), zero-filled OOB
    for (int e = tid; e < 1200; e += 128) {
        int i = e / 100;          // tile = k*4 + l
        int rc = e % 100;
        int l = i & 3;
        int r = rc / 10, cc = rc % 10;
        int Hl = c_lvlH[l], Wl = c_lvlW[l];
        int gx = sBx[i] - 4 + cc;
        int gy = sBy[i] - 4 + r;
        float v = 0.f;
        if (gx >= 0 && gx < Wl && gy >= 0 && gy < Hl) {
            const float* base;
            if (l == 0)      base = g_corr + (long)p * 3072;
            else if (l == 1) base = g_pyr1 + (long)p * 768;
            else if (l == 2) base = g_pyr2 + (long)p * 192;
            else             base = g_pyr3 + (long)p * 48;
            v = base[gy * Wl + gx];
        }
        sT[i][rc] = v;
    }
    __syncthreads();
    for (int c = tid; c < CORR_DIM; c += 128) {
        int l = c / 81, o = c % 81;
        int ty = o / 9, tx = o % 9;   // oy+4, ox+4 in [0,8]
        float acc = 0.f;
#pragma unroll
        for (int k = 0; k < 3; k++) {
            int i = k * 4 + l;
            float fxw = sFx[i], fyw = sFy[i];
            const float* T = sT[i];
            float s = (1.f - fxw) * (1.f - fyw) * T[ty * 10 + tx]
                    + fxw * (1.f - fyw) * T[ty * 10 + tx + 1]
                    + (1.f - fxw) * fyw * T[(ty + 1) * 10 + tx]
                    + fxw * fyw * T[(ty + 1) * 10 + tx + 1];
            acc += sWk[k] * s;
        }
        g_xin[c * HW + p] = acc;
    }
}

// ---------------------------------------------------------------------------
// Conv: bf16 tensor-core implicit GEMM over taps (mma.sync.m16n8k16).
// mode 4 = merged z+r (grid z = 2*SPLITK); mode 3 = h-conv, splitK=1 with
// fused relu + spatial-reduce epilogue (atomicAdd into g_feat).
// ---------------------------------------------------------------------------
__device__ __forceinline__ void conv_loadch(float pf[17], const float* inA, const float* inB,
                                            int C, int chunk, int sc, int sp0, int y0) {
    int cg = chunk * 16 + sc;
    const float* plane = (cg < 128) ? (inA + cg * HW)
                       : ((cg < C) ? (inB + (cg - 128) * HW) : (const float*)0);
#pragma unroll
    for (int k = 0; k < 17; k++) {
        int px = sp0 + k * 16;
        float v = 0.f;
        if (px < 264 && plane) {
            int row = px / 66, xcol = px % 66;
            int yy = y0 - 1 + row, xx = xcol - 1;
            if (yy >= 0 && yy < Hh && xx >= 0 && xx < Ww) v = plane[yy * Ww + xx];
        }
        pf[k] = v;
    }
}
__device__ __forceinline__ void conv_storech(float pf[17], unsigned short* s,
                                             int sc, int sp0) {
#pragma unroll
    for (int k = 0; k < 17; k++) {
        int px = sp0 + k * 16;
        if (px < 264)
            s[px * 18 + sc] = __bfloat16_as_ushort(__float2bfloat16(pf[k]));
    }
}

__global__ void __launch_bounds__(256, 2) k_convT(int mode, const float* __restrict__ bias) {
    const float* inA; const float* inB; const unsigned int* wA; float* outP; int nch, C;
    if (mode == 0)      { inA = g_h;   inB = g_xin; wA = g_wAz; outP = g_pA; nch = 33; C = GIN; }
    else if (mode == 1) { inA = g_h;   inB = g_xin; wA = g_wAr; outP = g_pB; nch = 33; C = GIN; }
    else if (mode == 2) { inA = g_rgh; inB = g_xin; wA = g_wAq; outP = g_pA; nch = 33; C = GIN; }
    else if (mode == 3) { inA = g_h;   inB = g_h;   wA = g_wAh; outP = g_pB; nch = 8;  C = 128; }
    else {
        inA = g_h; inB = g_xin; nch = 33; C = GIN;
        if (blockIdx.z < SPLITK) { wA = g_wAz; outP = g_pA; }
        else                     { wA = g_wAr; outP = g_pB; }
    }

    const int y0 = blockIdx.y * 2;
    const int ocBase = blockIdx.x * 64;
    const int ns = (mode == 3) ? 1 : SPLITK;
    const int kz = (int)blockIdx.z % SPLITK;
    const int ch0 = kz * nch / ns;
    const int ch1 = (kz + 1) * nch / ns;
    outP += kz * HIDDEN * HW;

    const int tid = threadIdx.x;
    const int lane = tid & 31;
    const int wid = tid >> 5;
    const int mf = wid & 3;
    const int nb = (wid >> 2) * 8;
    const int fg = (ocBase >> 4) + mf;

    const int sc = tid >> 4;
    const int sp0 = tid & 15;

    __shared__ unsigned short sIn[2][264 * 18];

    float acc[8][4];
#pragma unroll
    for (int i = 0; i < 8; i++)
#pragma unroll
        for (int j = 0; j < 4; j++) acc[i][j] = 0.f;

    float pf[17];
    conv_loadch(pf, inA, inB, C, ch0, sc, sp0, y0);
    conv_storech(pf, sIn[0], sc, sp0);
    __syncthreads();

    const uint4* wA4 = (const uint4*)wA;

    for (int ch = ch0; ch < ch1; ch++) {
        const int b = (ch - ch0) & 1;
        const bool more = (ch + 1 < ch1);
        if (more) conv_loadch(pf, inA, inB, C, ch + 1, sc, sp0, y0);

        uint4 Acur = wA4[((ch * 9 + 0) * 8 + fg) * 32 + lane];
#pragma unroll
        for (int tap = 0; tap < 9; tap++) {
            uint4 Anext = Acur;
            if (tap < 8) Anext = wA4[((ch * 9 + tap + 1) * 8 + fg) * 32 + lane];
            const int dy = tap / 3, dx = tap % 3;
#pragma unroll
            for (int nf = 0; nf < 8; nf++) {
                int n = (nb + nf) * 8 + (lane >> 2);
                int r = n >> 6, x = n & 63;
                int pxs = (r + dy) * 66 + x + dx;
                const unsigned short* bp = &sIn[b][pxs * 18 + (lane & 3) * 2];
                unsigned int b0 = *(const unsigned int*)bp;
                unsigned int b1 = *(const unsigned int*)(bp + 8);
                asm volatile(
                    "mma.sync.aligned.m16n8k16.row.col.f32.bf16.bf16.f32 "
                    "{%0,%1,%2,%3}, {%4,%5,%6,%7}, {%8,%9}, {%0,%1,%2,%3};"
                    : "+f"(acc[nf][0]), "+f"(acc[nf][1]),
                      "+f"(acc[nf][2]), "+f"(acc[nf][3])
                    : "r"(Acur.x), "r"(Acur.y), "r"(Acur.z), "r"(Acur.w),
                      "r"(b0), "r"(b1));
            }
            Acur = Anext;
        }
        if (more) conv_storech(pf, sIn[b ^ 1], sc, sp0);
        __syncthreads();
    }

    const int oc0 = ocBase + mf * 16 + (lane >> 2);
    if (mode == 3) {
        float b0v = bias[oc0];
        float b8v = bias[oc0 + 8];
        float sA = 0.f, sB = 0.f;
#pragma unroll
        for (int nf = 0; nf < 8; nf++) {
            sA += fmaxf(acc[nf][0] + b0v, 0.f) + fmaxf(acc[nf][1] + b0v, 0.f);
            sB += fmaxf(acc[nf][2] + b8v, 0.f) + fmaxf(acc[nf][3] + b8v, 0.f);
        }
        sA += __shfl_xor_sync(0xffffffff, sA, 1);
        sA += __shfl_xor_sync(0xffffffff, sA, 2);
        sB += __shfl_xor_sync(0xffffffff, sB, 1);
        sB += __shfl_xor_sync(0xffffffff, sB, 2);
        if ((lane & 3) == 0) {
            atomicAdd(&g_feat[oc0], sA);
            atomicAdd(&g_feat[oc0 + 8], sB);
        }
        return;
    }
#pragma unroll
    for (int nf = 0; nf < 8; nf++) {
        int n = (nb + nf) * 8 + (lane & 3) * 2;
        int r = n >> 6, x = n & 63;
        float* o0 = &outP[oc0 * HW + (y0 + r) * Ww + x];
        *(float2*)o0 = make_float2(acc[nf][0], acc[nf][1]);
        *(float2*)(o0 + 8 * HW) = make_float2(acc[nf][2], acc[nf][3]);
    }
}

__device__ __forceinline__ float sum6(const float* P, int i) {
    float s = P[i];
#pragma unroll
    for (int k = 1; k < SPLITK; k++) s += P[i + k * HIDDEN * HW];
    return s;
}

__global__ void k_comb_zr(const float* __restrict__ bz, const float* __restrict__ br) {
    int i = blockIdx.x * 256 + threadIdx.x;
    int oc = i / HW;
    float z = sum6(g_pA, i) + bz[oc];
    z = 1.f / (1.f + expf(-z));
    float rr = sum6(g_pB, i) + br[oc];
    rr = 1.f / (1.f + expf(-rr));
    g_zg[i] = z;
    g_rgh[i] = rr * g_h[i];
}

__global__ void k_comb_q(const float* __restrict__ bq) {
    int i = blockIdx.x * 256 + threadIdx.x;
    int oc = i / HW;
    float q = sum6(g_pA, i) + bq[oc];
    q = tanhf(q);
    float z = g_zg[i];
    g_h[i] = (1.f - z) * g_h[i] + z * q;
    if (i < HIDDEN) g_feat[i] = 0.f;
}

// pose update + next-iter sample prep (fused)
__global__ void k_pose(const float* __restrict__ Wfc, const float* __restrict__ bfc,
                       float* __restrict__ outp, int writeOut) {
    __shared__ float red[128];
    __shared__ float sdelta[7];
    __shared__ float sP[7];
    int t = threadIdx.x;
    float fm = g_feat[t] * (1.0f / 3072.0f);
    for (int j = 0; j < 7; j++) {
        red[t] = fm * Wfc[t * 7 + j];
        __syncthreads();
        for (int s = 64; s > 0; s >>= 1) {
            if (t < s) red[t] += red[t + s];
            __syncthreads();
        }
        if (t == 0) sdelta[j] = 0.01f * (red[0] + bfc[j]);
        __syncthreads();
    }
    if (t == 0) {
        float qc[4] = {g_pose[0], g_pose[1], g_pose[2], g_pose[3]};
        float tc[3] = {g_pose[4], g_pose[5], g_pose[6]};
        float dq[4] = {1.f + sdelta[0], sdelta[1], sdelta[2], sdelta[3]};
        float inv = rsqrtf(dq[0]*dq[0] + dq[1]*dq[1] + dq[2]*dq[2] + dq[3]*dq[3]);
        dq[0] *= inv; dq[1] *= inv; dq[2] *= inv; dq[3] *= inv;
        float dv[3] = {sdelta[4], sdelta[5], sdelta[6]};
        float rv[3];
        qapply_d(qc, dv, rv);
        float tn[3] = {tc[0] + rv[0], tc[1] + rv[1], tc[2] + rv[2]};
        float qn[4];
        qmul_d(qc, dq, qn);
        float inv2 = rsqrtf(qn[0]*qn[0] + qn[1]*qn[1] + qn[2]*qn[2] + qn[3]*qn[3]);
        qn[0] *= inv2; qn[1] *= inv2; qn[2] *= inv2; qn[3] *= inv2;
        g_pose[0] = qn[0]; g_pose[1] = qn[1]; g_pose[2] = qn[2]; g_pose[3] = qn[3];
        g_pose[4] = tn[0]; g_pose[5] = tn[1]; g_pose[6] = tn[2];
        sP[0] = qn[0]; sP[1] = qn[1]; sP[2] = qn[2]; sP[3] = qn[3];
        sP[4] = tn[0]; sP[5] = tn[1]; sP[6] = tn[2];
        if (writeOut) {
            outp[0] = qn[0]; outp[1] = qn[1]; outp[2] = qn[2]; outp[3] = qn[3];
            outp[4] = tn[0]; outp[5] = tn[1]; outp[6] = tn[2];
        }
    }
    __syncthreads();
    if (t < NSAMP) {
        g_conf[t] = 0.f;
        float p[7];
#pragma unroll
        for (int k = 0; k < 7; k++) p[k] = sP[k];
        sample_body(t, p);
    }
}

extern "C" void kernel_launch(void* const* d_in, const int* in_sizes, int n_in,
                              void* d_out, int out_size) {
    const float* fmap_rgb   = (const float*)d_in[0];
    const float* fmap_depth = (const float*)d_in[1];
    const float* depth      = (const float*)d_in[2];
    const float* context    = (const float*)d_in[3];
    const float* intr       = (const float*)d_in[4];
    const float* Wz  = (const float*)d_in[5];
    const float* bz  = (const float*)d_in[6];
    const float* Wr  = (const float*)d_in[7];
    const float* br  = (const float*)d_in[8];
    const float* Wq  = (const float*)d_in[9];
    const float* bq  = (const float*)d_in[10];
    const float* Wh  = (const float*)d_in[11];
    const float* bh  = (const float*)d_in[12];
    const float* Wfc = (const float*)d_in[13];
    const float* bfc = (const float*)d_in[14];
    float* outp = (float*)d_out;

    dim3 cgrid(2, 24, SPLITK);
    dim3 cgrid2(2, 24, 2 * SPLITK);
    dim3 cgridH(2, 24, 1);

    k_setup<<<1536, 256>>>(depth, intr, context);           // 0
    k_wTall<<<3852, 256>>>(Wz, Wr, Wq, Wh);                 // 1
    k_corrT<<<dim3(48, 48), 256>>>(fmap_depth, fmap_rgb);   // 2
    k_pool<<<9216, 256>>>(1);                               // 3
    k_pool<<<2304, 256>>>(2);                               // 4
    k_pool<<<576, 256>>>(3);                                // 5
    k_sat<<<3072, 128>>>(0);
    k_sat<<<3072, 128>>>(1);
    k_sat<<<3072, 128>>>(2);
    k_sat<<<3072, 128>>>(3);

    for (int it = 0; it < 4; it++) {
        k_conf<<<dim3(37, 8), 256>>>();
        k_fused<<<3072, 128>>>();
        k_convT<<<cgrid2, 256>>>(4, bz);         // z + r merged
        k_comb_zr<<<1536, 256>>>(bz, br);
        k_convT<<<cgrid, 256>>>(2, bq);
        k_comb_q<<<1536, 256>>>(bq);
        k_convT<<<cgridH, 256>>>(3, bh);         // h-conv + fused relu/reduce
        k_pose<<<1, 128>>>(Wfc, bfc, outp, it == 3 ? 1 : 0);
    }
}